// round 6
// baseline (speedup 1.0000x reference)
#include <cuda_runtime.h>

#define HID 1024
#define NSAMP 1024
#define TSTEPS 98
#define G 16           // samples per cluster (2 CTAs share them)
#define NTHR 256       // threads per CTA; thread owns units hA=512*rank+2tid, hB=hA+1
#define NCTA 128       // 64 clusters x 2 CTAs

__device__ float g_W2T[HID * HID];
__device__ float g_W3T[HID * HID];
__device__ float g_fr[3];
__device__ float g_out[NSAMP * 10];

// ---------------------------------------------------------------------------
__global__ void prep_kernel(const float* __restrict__ W2,
                            const float* __restrict__ W3) {
    __shared__ float tile[32][33];
    const float* src = (blockIdx.z == 0) ? W2 : W3;
    float* dst = (blockIdx.z == 0) ? g_W2T : g_W3T;
    int bx = blockIdx.x * 32, by = blockIdx.y * 32;
    tile[threadIdx.y][threadIdx.x] = src[(by + threadIdx.y) * HID + bx + threadIdx.x];
    __syncthreads();
    dst[(bx + threadIdx.y) * HID + by + threadIdx.x] = tile[threadIdx.x][threadIdx.y];
    int t = threadIdx.y * 32 + threadIdx.x;
    if (blockIdx.z == 0 && blockIdx.y == 0 && blockIdx.x < 10)
        g_out[blockIdx.x * 1024 + t] = 0.0f;
    if (blockIdx.x == 0 && blockIdx.y == 0 && blockIdx.z == 0 && t < 3)
        g_fr[t] = 0.0f;
}

// ---------------------------------------------------------------------------
static __device__ __forceinline__ unsigned long long addf32x2(
    unsigned long long a, unsigned long long b) {
    unsigned long long o;
    asm("add.rn.f32x2 %0, %1, %2;" : "=l"(o) : "l"(a), "l"(b));
    return o;
}

static __device__ __forceinline__ unsigned spread4(unsigned m) {
    return ((m & 0xFu) * 0x00204081u) & 0x01010101u;
}

static __device__ __forceinline__ unsigned bytesum(unsigned v, unsigned c) {
    unsigned ones = 0x01010101u;
    unsigned r;
    asm("dp4a.u32.u32 %0, %1, %2, %3;" : "=r"(r) : "r"(v), "r"(ones), "r"(c));
    return r;
}

static __device__ __forceinline__ unsigned smem_u32(const void* p) {
    unsigned a;
    asm("{ .reg .u64 t; cvta.to.shared.u64 t, %1; cvt.u32.u64 %0, t; }"
        : "=r"(a) : "l"(p));
    return a;
}

static __device__ __forceinline__ void st_peer_u32(unsigned localAddr,
                                                   unsigned peerRank,
                                                   unsigned val) {
    unsigned r;
    asm volatile("mapa.shared::cluster.u32 %0, %1, %2;"
                 : "=r"(r) : "r"(localAddr), "r"(peerRank));
    asm volatile("st.shared::cluster.u32 [%0], %1;"
                 :: "r"(r), "r"(val) : "memory");
}

#define CLUSTER_SYNC()                                                  \
    do {                                                                \
        asm volatile("barrier.cluster.arrive.aligned;" ::: "memory");   \
        asm volatile("barrier.cluster.wait.aligned;" ::: "memory");     \
    } while (0)

// exclusive scan over 256 threads (8 warps); returns total to all threads
static __device__ __forceinline__ void block_scan(int v, int tid, int* s_warp,
                                                  int& excl, int& total) {
    int lane = tid & 31, wid = tid >> 5;
    int x = v;
#pragma unroll
    for (int o = 1; o < 32; o <<= 1) {
        int y = __shfl_up_sync(0xffffffffu, x, o);
        if (lane >= o) x += y;
    }
    __syncthreads();
    if (lane == 31) s_warp[wid] = x;
    __syncthreads();
    int pre = 0, tot = 0;
#pragma unroll
    for (int w = 0; w < 8; w++) {
        int sw = s_warp[w];
        pre += (w < wid) ? sw : 0;
        tot += sw;
    }
    excl = pre + x - v;
    total = tot;
}

union F2U { unsigned long long u; float2 f; };

// membrane update for the 2 owned units across 16 samples (drive packed f32x2)
static __device__ __forceinline__ void upd2(float* mA, float* mB,
                                            const unsigned long long* d,
                                            bool elA, bool elB,
                                            unsigned& pA, unsigned& pB) {
    unsigned a = 0, b = 0;
#pragma unroll
    for (int g = 0; g < G; g++) {
        F2U u;
        u.u = d[g];
        if (elA) {
            float base = ((pA >> g) & 1) ? 0.0f : mA[g] * 0.5f;
            float nm = base + u.f.x;
            mA[g] = nm;
            if (nm > 0.5f) a |= (1u << g);
        }
        if (elB) {
            float base = ((pB >> g) & 1) ? 0.0f : mB[g] * 0.5f;
            float nm = base + u.f.y;
            mB[g] = nm;
            if (nm > 0.5f) b |= (1u << g);
        }
    }
    pA = a;
    pB = b;
}

// 16 predicated packed adds for one row (mask in bits [10:26) of e)
#define ACC16(e, wv)                                         \
    do {                                                     \
        unsigned _m = (e) >> 10;                             \
        if (_m & 0x0001u) acc[0]  = addf32x2(acc[0],  (wv)); \
        if (_m & 0x0002u) acc[1]  = addf32x2(acc[1],  (wv)); \
        if (_m & 0x0004u) acc[2]  = addf32x2(acc[2],  (wv)); \
        if (_m & 0x0008u) acc[3]  = addf32x2(acc[3],  (wv)); \
        if (_m & 0x0010u) acc[4]  = addf32x2(acc[4],  (wv)); \
        if (_m & 0x0020u) acc[5]  = addf32x2(acc[5],  (wv)); \
        if (_m & 0x0040u) acc[6]  = addf32x2(acc[6],  (wv)); \
        if (_m & 0x0080u) acc[7]  = addf32x2(acc[7],  (wv)); \
        if (_m & 0x0100u) acc[8]  = addf32x2(acc[8],  (wv)); \
        if (_m & 0x0200u) acc[9]  = addf32x2(acc[9],  (wv)); \
        if (_m & 0x0400u) acc[10] = addf32x2(acc[10], (wv)); \
        if (_m & 0x0800u) acc[11] = addf32x2(acc[11], (wv)); \
        if (_m & 0x1000u) acc[12] = addf32x2(acc[12], (wv)); \
        if (_m & 0x2000u) acc[13] = addf32x2(acc[13], (wv)); \
        if (_m & 0x4000u) acc[14] = addf32x2(acc[14], (wv)); \
        if (_m & 0x8000u) acc[15] = addf32x2(acc[15], (wv)); \
    } while (0)

// union-row gather over one list segment; accumulates into acc (no init).
// base = (ull*)WT + rank*256 + tid; row h slice at base + (h << 9).
static __device__ __forceinline__ void gather_acc(
    const unsigned* __restrict__ list, int cnt,
    const unsigned long long* __restrict__ base, unsigned long long acc[G]) {
    const int nb = cnt >> 2;
    if (nb > 0) {
        uint4 c = *reinterpret_cast<const uint4*>(list);
        unsigned e0 = c.x, e1 = c.y, e2 = c.z, e3 = c.w;
        unsigned long long w0 = __ldg(base + ((e0 & 1023u) << 9));
        unsigned long long w1 = __ldg(base + ((e1 & 1023u) << 9));
        unsigned long long w2 = __ldg(base + ((e2 & 1023u) << 9));
        unsigned long long w3 = __ldg(base + ((e3 & 1023u) << 9));
        for (int b = 0; b < nb; b++) {
            unsigned f0 = e0, f1 = e1, f2 = e2, f3 = e3;
            unsigned long long v0 = w0, v1 = w1, v2 = w2, v3 = w3;
            if (b + 1 < nb) {
                uint4 n = *reinterpret_cast<const uint4*>(list + 4 * (b + 1));
                e0 = n.x; e1 = n.y; e2 = n.z; e3 = n.w;
                w0 = __ldg(base + ((e0 & 1023u) << 9));
                w1 = __ldg(base + ((e1 & 1023u) << 9));
                w2 = __ldg(base + ((e2 & 1023u) << 9));
                w3 = __ldg(base + ((e3 & 1023u) << 9));
            }
            ACC16(f0, v0);
            ACC16(f1, v1);
            ACC16(f2, v2);
            ACC16(f3, v3);
        }
    }
    for (int i = nb << 2; i < cnt; i++) {
        unsigned e = list[i];
        unsigned long long wv = __ldg(base + ((e & 1023u) << 9));
        ACC16(e, wv);
    }
}

// ---------------------------------------------------------------------------
__global__ void __launch_bounds__(NTHR) __cluster_dims__(2, 1, 1)
snn_kernel(const float* __restrict__ input,
           const float* __restrict__ W1, const float* __restrict__ b1,
           const float* __restrict__ b2, const float* __restrict__ b3,
           const float* __restrict__ W4,
           float* __restrict__ out) {
    __shared__ __align__(16) unsigned listA[1024];
    __shared__ __align__(16) unsigned listB[1024];
    __shared__ int s_warp[8];
    __shared__ float xsh[G * 8];
    __shared__ float4 s_red4[8];
    __shared__ unsigned cnts[4];  // [0..1]: list A counts, [2..3]: list B
    __shared__ unsigned long long dcsh[G * NTHR];  // 32KB const layer-1 drive

    const int tid = threadIdx.x;
    const unsigned rank = blockIdx.x & 1u;
    const unsigned prank = rank ^ 1u;
    const int n0 = (blockIdx.x >> 1) * G;
    const int hA = (int)rank * 512 + 2 * tid, hB = hA + 1;

    int uA = (98 - (hA % 98)) % 98;
    int uB = (98 - (hB % 98)) % 98;
    int r3A = uA % 3, r3B = uB % 3;

    float m1A[G], m1B[G], m2A[G], m2B[G], m3A[G], m3B[G];
#pragma unroll
    for (int g = 0; g < G; g++) {
        m1A[g] = 0; m1B[g] = 0; m2A[g] = 0;
        m2B[g] = 0; m3A[g] = 0; m3B[g] = 0;
    }
    unsigned p1a = 0, p1b = 0, p2a = 0, p2b = 0, p3a = 0, p3b = 0;
    unsigned ss1a[4] = {0,0,0,0}, ss1b[4] = {0,0,0,0};
    unsigned ss2a[4] = {0,0,0,0}, ss2b[4] = {0,0,0,0};
    unsigned ss3a[4] = {0,0,0,0}, ss3b[4] = {0,0,0,0};

    F2U bp2, bp3;
    bp2.f = make_float2(__ldg(b2 + hA), __ldg(b2 + hB));
    bp3.f = make_float2(__ldg(b3 + hA), __ldg(b3 + hB));

    const float4* W14 = reinterpret_cast<const float4*>(W1);
    const unsigned long long* base2 =
        reinterpret_cast<const unsigned long long*>(g_W2T) + rank * 256 + tid;
    const unsigned long long* base3 =
        reinterpret_cast<const unsigned long long*>(g_W3T) + rank * 256 + tid;

    // constant layer-1 drive (t >= 12 uses input slice at 776)
    if (tid < G * 8)
        xsh[tid] = __ldg(input + (n0 + (tid >> 3)) * 784 + 776 + (tid & 7));
    __syncthreads();
    {
        float4 wa0 = __ldg(W14 + hA * 2), wa1 = __ldg(W14 + hA * 2 + 1);
        float4 wb0 = __ldg(W14 + hB * 2), wb1 = __ldg(W14 + hB * 2 + 1);
        float ba = __ldg(b1 + hA), bb = __ldg(b1 + hB);
#pragma unroll
        for (int g = 0; g < G; g++) {
            const float* x = &xsh[g * 8];
            float sa = ba + x[0] * wa0.x + x[1] * wa0.y + x[2] * wa0.z +
                       x[3] * wa0.w + x[4] * wa1.x + x[5] * wa1.y +
                       x[6] * wa1.z + x[7] * wa1.w;
            float sb = bb + x[0] * wb0.x + x[1] * wb0.y + x[2] * wb0.z +
                       x[3] * wb0.w + x[4] * wb1.x + x[5] * wb1.y +
                       x[6] * wb1.z + x[7] * wb1.w;
            F2U u;
            u.f = make_float2(sa, sb);
            dcsh[g * NTHR + tid] = u.u;
        }
    }
    __syncthreads();

    for (int t = 0; t < TSTEPS; t++) {
        // ---------- layer 1 drive ----------
        unsigned long long d1[G];
        if (t < 12) {
            if (tid < G * 8)
                xsh[tid] =
                    __ldg(input + (n0 + (tid >> 3)) * 784 + t * 8 + (tid & 7));
            __syncthreads();
            float4 wa0 = __ldg(W14 + hA * 2), wa1 = __ldg(W14 + hA * 2 + 1);
            float4 wb0 = __ldg(W14 + hB * 2), wb1 = __ldg(W14 + hB * 2 + 1);
            float ba = __ldg(b1 + hA), bb = __ldg(b1 + hB);
#pragma unroll
            for (int g = 0; g < G; g++) {
                const float* x = &xsh[g * 8];
                float sa = ba + x[0] * wa0.x + x[1] * wa0.y + x[2] * wa0.z +
                           x[3] * wa0.w + x[4] * wa1.x + x[5] * wa1.y +
                           x[6] * wa1.z + x[7] * wa1.w;
                float sb = bb + x[0] * wb0.x + x[1] * wb0.y + x[2] * wb0.z +
                           x[3] * wb0.w + x[4] * wb1.x + x[5] * wb1.y +
                           x[6] * wb1.z + x[7] * wb1.w;
                F2U u;
                u.f = make_float2(sa, sb);
                d1[g] = u.u;
            }
            __syncthreads();
        } else {
#pragma unroll
            for (int g = 0; g < G; g++) d1[g] = dcsh[g * NTHR + tid];
        }

        // ---------- layer 1 update (cycle 2) ----------
        upd2(m1A, m1B, d1, (uA & 1) == 0, (uB & 1) == 0, p1a, p1b);
#pragma unroll
        for (int w = 0; w < 4; w++) {
            ss1a[w] += spread4(p1a >> (4 * w));
            ss1b[w] += spread4(p1b >> (4 * w));
        }

        int excl, cnt;
        block_scan((p1a ? 1 : 0) + (p1b ? 1 : 0), tid, s_warp, excl, cnt);
        {
            int p = (int)rank * 512 + excl;
            if (p1a) {
                unsigned v = (p1a << 10) | (unsigned)hA;
                listA[p] = v;
                st_peer_u32(smem_u32(&listA[p]), prank, v);
                p++;
            }
            if (p1b) {
                unsigned v = (p1b << 10) | (unsigned)hB;
                listA[p] = v;
                st_peer_u32(smem_u32(&listA[p]), prank, v);
            }
        }
        if (tid == 0) {
            cnts[rank] = (unsigned)cnt;
            st_peer_u32(smem_u32(&cnts[rank]), prank, (unsigned)cnt);
        }
        CLUSTER_SYNC();

        // ---------- layer 2: gather (both halves) + update (cycle 3) -------
        int c0 = (int)cnts[0], c1n = (int)cnts[1];
        unsigned long long acc[G];
#pragma unroll
        for (int g = 0; g < G; g++) acc[g] = bp2.u;
        gather_acc(listA, c0, base2, acc);
        gather_acc(listA + 512, c1n, base2, acc);

        upd2(m2A, m2B, acc, r3A == 0, r3B == 0, p2a, p2b);
#pragma unroll
        for (int w = 0; w < 4; w++) {
            ss2a[w] += spread4(p2a >> (4 * w));
            ss2b[w] += spread4(p2b >> (4 * w));
        }

        block_scan((p2a ? 1 : 0) + (p2b ? 1 : 0), tid, s_warp, excl, cnt);
        {
            int p = (int)rank * 512 + excl;
            if (p2a) {
                unsigned v = (p2a << 10) | (unsigned)hA;
                listB[p] = v;
                st_peer_u32(smem_u32(&listB[p]), prank, v);
                p++;
            }
            if (p2b) {
                unsigned v = (p2b << 10) | (unsigned)hB;
                listB[p] = v;
                st_peer_u32(smem_u32(&listB[p]), prank, v);
            }
        }
        if (tid == 0) {
            cnts[2 + rank] = (unsigned)cnt;
            st_peer_u32(smem_u32(&cnts[2 + rank]), prank, (unsigned)cnt);
        }
        CLUSTER_SYNC();

        // ---------- layer 3: gather + update (cycle 4) ----------
        c0 = (int)cnts[2];
        c1n = (int)cnts[3];
#pragma unroll
        for (int g = 0; g < G; g++) acc[g] = bp3.u;
        gather_acc(listB, c0, base3, acc);
        gather_acc(listB + 512, c1n, base3, acc);

        upd2(m3A, m3B, acc, (uA & 3) == 0, (uB & 3) == 0, p3a, p3b);
#pragma unroll
        for (int w = 0; w < 4; w++) {
            ss3a[w] += spread4(p3a >> (4 * w));
            ss3b[w] += spread4(p3b >> (4 * w));
        }

        if (++uA == 98) { uA = 0; r3A = 0; } else if (++r3A == 3) r3A = 0;
        if (++uB == 98) { uB = 0; r3B = 0; } else if (++r3B == 3) r3B = 0;
    }

    // ------------------------- epilogue -------------------------
    float s3A[G], s3B[G];
#pragma unroll
    for (int g = 0; g < G; g++) {
        s3A[g] = (float)((ss3a[g >> 2] >> (8 * (g & 3))) & 255u);
        s3B[g] = (float)((ss3b[g >> 2] >> (8 * (g & 3))) & 255u);
    }

    // hidden_spk = ss / 98 (this CTA's 512 units x 16 samples)
#pragma unroll
    for (int g = 0; g < G; g++) {
        float a1 = (float)((ss1a[g >> 2] >> (8 * (g & 3))) & 255u);
        float c1 = (float)((ss1b[g >> 2] >> (8 * (g & 3))) & 255u);
        float a2 = (float)((ss2a[g >> 2] >> (8 * (g & 3))) & 255u);
        float c2 = (float)((ss2b[g >> 2] >> (8 * (g & 3))) & 255u);
        const float inv = 1.0f / 98.0f;
        float2* o1 = reinterpret_cast<float2*>(out + 10240 + 0 * 1048576 +
                                               (n0 + g) * HID + hA);
        float2* o2 = reinterpret_cast<float2*>(out + 10240 + 1 * 1048576 +
                                               (n0 + g) * HID + hA);
        float2* o3 = reinterpret_cast<float2*>(out + 10240 + 2 * 1048576 +
                                               (n0 + g) * HID + hA);
        *o1 = make_float2(a1 * inv, c1 * inv);
        *o2 = make_float2(a2 * inv, c2 * inv);
        *o3 = make_float2(s3A[g] * inv, s3B[g] * inv);
    }

    const int lane = tid & 31, wid = tid >> 5;

    // partial outputs: (ss3_slice @ W4_slice^T) -> atomic into g_out
    for (int o = 0; o < 10; o++) {
        float wa = __ldg(W4 + o * HID + hA);
        float wb = __ldg(W4 + o * HID + hB);
#pragma unroll
        for (int q = 0; q < 4; q++) {
            float4 v;
            v.x = s3A[q * 4 + 0] * wa + s3B[q * 4 + 0] * wb;
            v.y = s3A[q * 4 + 1] * wa + s3B[q * 4 + 1] * wb;
            v.z = s3A[q * 4 + 2] * wa + s3B[q * 4 + 2] * wb;
            v.w = s3A[q * 4 + 3] * wa + s3B[q * 4 + 3] * wb;
#pragma unroll
            for (int off = 16; off > 0; off >>= 1) {
                v.x += __shfl_down_sync(0xffffffffu, v.x, off);
                v.y += __shfl_down_sync(0xffffffffu, v.y, off);
                v.z += __shfl_down_sync(0xffffffffu, v.z, off);
                v.w += __shfl_down_sync(0xffffffffu, v.w, off);
            }
            if (lane == 0) s_red4[wid] = v;
            __syncthreads();
            if (tid == 0) {
                float4 s = make_float4(0, 0, 0, 0);
#pragma unroll
                for (int w = 0; w < 8; w++) {
                    s.x += s_red4[w].x; s.y += s_red4[w].y;
                    s.z += s_red4[w].z; s.w += s_red4[w].w;
                }
                atomicAdd(&g_out[(n0 + q * 4 + 0) * 10 + o], s.x);
                atomicAdd(&g_out[(n0 + q * 4 + 1) * 10 + o], s.y);
                atomicAdd(&g_out[(n0 + q * 4 + 2) * 10 + o], s.z);
                atomicAdd(&g_out[(n0 + q * 4 + 3) * 10 + o], s.w);
            }
            __syncthreads();
        }
    }

    // layer firing-rate partial sums (exact integers in fp32)
    unsigned c1 = 0, c2 = 0, c3 = 0;
#pragma unroll
    for (int w = 0; w < 4; w++) {
        c1 = bytesum(ss1a[w], c1); c1 = bytesum(ss1b[w], c1);
        c2 = bytesum(ss2a[w], c2); c2 = bytesum(ss2b[w], c2);
        c3 = bytesum(ss3a[w], c3); c3 = bytesum(ss3b[w], c3);
    }
    {
        float4 v = make_float4((float)c1, (float)c2, (float)c3, 0.0f);
#pragma unroll
        for (int off = 16; off > 0; off >>= 1) {
            v.x += __shfl_down_sync(0xffffffffu, v.x, off);
            v.y += __shfl_down_sync(0xffffffffu, v.y, off);
            v.z += __shfl_down_sync(0xffffffffu, v.z, off);
        }
        if (lane == 0) s_red4[wid] = v;
        __syncthreads();
        if (tid == 0) {
            float s0 = 0, s1 = 0, s2 = 0;
#pragma unroll
            for (int w = 0; w < 8; w++) {
                s0 += s_red4[w].x; s1 += s_red4[w].y; s2 += s_red4[w].z;
            }
            atomicAdd(&g_fr[0], s0);
            atomicAdd(&g_fr[1], s1);
            atomicAdd(&g_fr[2], s2);
        }
    }
    CLUSTER_SYNC();  // no CTA exits while peer may still target its SMEM
}

// ---------------------------------------------------------------------------
__global__ void finalize_kernel(const float* __restrict__ b4,
                                float* __restrict__ out) {
    int idx = blockIdx.x * blockDim.x + threadIdx.x;
    if (idx < NSAMP * 10) {
        int o = idx % 10;
        out[idx] = g_out[idx] / 98.0f + __ldg(b4 + o);
    }
    if (idx < 3) out[3155968 + idx] = g_fr[idx] / 102760448.0f;
}

extern "C" void kernel_launch(void* const* d_in, const int* in_sizes, int n_in,
                              void* d_out, int out_size) {
    const float* input = (const float*)d_in[0];
    const float* W1 = (const float*)d_in[1];
    const float* b1 = (const float*)d_in[2];
    const float* W2 = (const float*)d_in[3];
    const float* b2 = (const float*)d_in[4];
    const float* W3 = (const float*)d_in[5];
    const float* b3 = (const float*)d_in[6];
    const float* W4 = (const float*)d_in[7];
    const float* b4 = (const float*)d_in[8];
    (void)in_sizes; (void)n_in; (void)out_size;

    dim3 pgrid(HID / 32, HID / 32, 2);
    prep_kernel<<<pgrid, dim3(32, 32)>>>(W2, W3);
    snn_kernel<<<NCTA, NTHR>>>(input, W1, b1, b2, b3, W4, (float*)d_out);
    finalize_kernel<<<10, 1024>>>(b4, (float*)d_out);
}

// round 7
// speedup vs baseline: 1.4267x; 1.4267x over previous
#include <cuda_runtime.h>

#define HID 1024
#define NSAMP 1024
#define TSTEPS 98
#define G 8            // samples per CTA
#define NTHR 256       // threads per CTA; thread owns units 4*tid .. 4*tid+3
#define NCTA (NSAMP / G)

__device__ float g_W2T[HID * HID];
__device__ float g_W3T[HID * HID];
__device__ float g_fr[3];

// ---------------------------------------------------------------------------
__global__ void prep_kernel(const float* __restrict__ W2,
                            const float* __restrict__ W3) {
    __shared__ float tile[32][33];
    const float* src = (blockIdx.z == 0) ? W2 : W3;
    float* dst = (blockIdx.z == 0) ? g_W2T : g_W3T;
    int bx = blockIdx.x * 32, by = blockIdx.y * 32;
    tile[threadIdx.y][threadIdx.x] = src[(by + threadIdx.y) * HID + bx + threadIdx.x];
    __syncthreads();
    dst[(bx + threadIdx.y) * HID + by + threadIdx.x] = tile[threadIdx.x][threadIdx.y];
    if (blockIdx.x == 0 && blockIdx.y == 0 && blockIdx.z == 0 &&
        threadIdx.y == 0 && threadIdx.x < 3)
        g_fr[threadIdx.x] = 0.0f;
}

// ---------------------------------------------------------------------------
static __device__ __forceinline__ unsigned long long addf32x2(
    unsigned long long a, unsigned long long b) {
    unsigned long long o;
    asm("add.rn.f32x2 %0, %1, %2;" : "=l"(o) : "l"(a), "l"(b));
    return o;
}

static __device__ __forceinline__ unsigned spread4(unsigned m) {
    return ((m & 0xFu) * 0x00204081u) & 0x01010101u;
}

static __device__ __forceinline__ unsigned bytesum(unsigned v, unsigned c) {
    unsigned ones = 0x01010101u;
    unsigned r;
    asm("dp4a.u32.u32 %0, %1, %2, %3;" : "=r"(r) : "r"(v), "r"(ones), "r"(c));
    return r;
}

// exclusive scan over 256 threads (8 warps); returns total to all threads
static __device__ __forceinline__ void block_scan(int v, int tid, int* s_warp,
                                                  int& excl, int& total) {
    int lane = tid & 31, wid = tid >> 5;
    int x = v;
#pragma unroll
    for (int o = 1; o < 32; o <<= 1) {
        int y = __shfl_up_sync(0xffffffffu, x, o);
        if (lane >= o) x += y;
    }
    __syncthreads();
    if (lane == 31) s_warp[wid] = x;
    __syncthreads();
    int pre = 0, tot = 0;
#pragma unroll
    for (int w = 0; w < 8; w++) {
        int sw = s_warp[w];
        pre += (w < wid) ? sw : 0;
        tot += sw;
    }
    excl = pre + x - v;
    total = tot;
}

union F2U { unsigned long long u; float2 f; };
union F4U { float4 f; unsigned long long u[2]; };

// membrane update for a unit pair (packed drive), per-unit eligibility
static __device__ __forceinline__ void upd_pair(float* mX, float* mY,
                                                const unsigned long long* d,
                                                bool elX, bool elY,
                                                unsigned& pX, unsigned& pY) {
    unsigned a = 0, b = 0;
#pragma unroll
    for (int g = 0; g < G; g++) {
        F2U u;
        u.u = d[g];
        if (elX) {
            float base = ((pX >> g) & 1) ? 0.0f : mX[g] * 0.5f;
            float nm = base + u.f.x;
            mX[g] = nm;
            if (nm > 0.5f) a |= (1u << g);
        }
        if (elY) {
            float base = ((pY >> g) & 1) ? 0.0f : mY[g] * 0.5f;
            float nm = base + u.f.y;
            mY[g] = nm;
            if (nm > 0.5f) b |= (1u << g);
        }
    }
    if (elX) pX = a; else pX = 0;
    if (elY) pY = b; else pY = 0;
}

// 8 samples x (1 pred test + 2 packed adds) for one 4-unit row slice
#define ACCQ(e, w)                                                          \
    do {                                                                    \
        unsigned _m = (e) >> 10;                                            \
        if (_m & 1u)   { accL[0] = addf32x2(accL[0], (w).u[0]);             \
                         accH[0] = addf32x2(accH[0], (w).u[1]); }           \
        if (_m & 2u)   { accL[1] = addf32x2(accL[1], (w).u[0]);             \
                         accH[1] = addf32x2(accH[1], (w).u[1]); }           \
        if (_m & 4u)   { accL[2] = addf32x2(accL[2], (w).u[0]);             \
                         accH[2] = addf32x2(accH[2], (w).u[1]); }           \
        if (_m & 8u)   { accL[3] = addf32x2(accL[3], (w).u[0]);             \
                         accH[3] = addf32x2(accH[3], (w).u[1]); }           \
        if (_m & 16u)  { accL[4] = addf32x2(accL[4], (w).u[0]);             \
                         accH[4] = addf32x2(accH[4], (w).u[1]); }           \
        if (_m & 32u)  { accL[5] = addf32x2(accL[5], (w).u[0]);             \
                         accH[5] = addf32x2(accH[5], (w).u[1]); }           \
        if (_m & 64u)  { accL[6] = addf32x2(accL[6], (w).u[0]);             \
                         accH[6] = addf32x2(accH[6], (w).u[1]); }           \
        if (_m & 128u) { accL[7] = addf32x2(accL[7], (w).u[0]);             \
                         accH[7] = addf32x2(accH[7], (w).u[1]); }           \
    } while (0)

// union-row gather, 4 rows in flight; base = (float4*)WT + tid, row at h<<8
static __device__ __forceinline__ void gather(const unsigned* __restrict__ list,
                                              int cnt,
                                              const float4* __restrict__ base,
                                              unsigned long long accL[G],
                                              unsigned long long accH[G]) {
    const int nb = cnt >> 2;
    if (nb > 0) {
        uint4 c = *reinterpret_cast<const uint4*>(list);
        unsigned e0 = c.x, e1 = c.y, e2 = c.z, e3 = c.w;
        F4U w0, w1, w2, w3;
        w0.f = __ldg(base + ((e0 & 1023u) << 8));
        w1.f = __ldg(base + ((e1 & 1023u) << 8));
        w2.f = __ldg(base + ((e2 & 1023u) << 8));
        w3.f = __ldg(base + ((e3 & 1023u) << 8));
        for (int b = 0; b < nb; b++) {
            unsigned f0 = e0, f1 = e1, f2 = e2, f3 = e3;
            F4U v0 = w0, v1 = w1, v2 = w2, v3 = w3;
            if (b + 1 < nb) {
                uint4 n = *reinterpret_cast<const uint4*>(list + 4 * (b + 1));
                e0 = n.x; e1 = n.y; e2 = n.z; e3 = n.w;
                w0.f = __ldg(base + ((e0 & 1023u) << 8));
                w1.f = __ldg(base + ((e1 & 1023u) << 8));
                w2.f = __ldg(base + ((e2 & 1023u) << 8));
                w3.f = __ldg(base + ((e3 & 1023u) << 8));
            }
            ACCQ(f0, v0);
            ACCQ(f1, v1);
            ACCQ(f2, v2);
            ACCQ(f3, v3);
        }
    }
    for (int i = nb << 2; i < cnt; i++) {
        unsigned e = list[i];
        F4U wv;
        wv.f = __ldg(base + ((e & 1023u) << 8));
        ACCQ(e, wv);
    }
}

// ---------------------------------------------------------------------------
__global__ void __launch_bounds__(NTHR) snn_kernel(
    const float* __restrict__ input,
    const float* __restrict__ W1, const float* __restrict__ b1,
    const float* __restrict__ b2, const float* __restrict__ b3,
    const float* __restrict__ W4, const float* __restrict__ b4,
    float* __restrict__ out) {
    __shared__ __align__(16) unsigned listA[HID];
    __shared__ __align__(16) unsigned listB[HID];
    __shared__ int s_warp[8];
    __shared__ float xsh[G * 8];
    __shared__ float4 s_red4[8];
    __shared__ __align__(16) ulonglong2 dcsh[G * NTHR];  // 32KB const L1 drive

    const int tid = threadIdx.x;
    const int n0 = blockIdx.x * G;
    const int h0 = 4 * tid;

    // per-unit phase counters: u_k = (t - (h0+k)) mod 98, and u mod 3
    int u[4], r3[4];
#pragma unroll
    for (int k = 0; k < 4; k++) {
        u[k] = (98 - ((h0 + k) % 98)) % 98;
        r3[k] = u[k] % 3;
    }

    float m1[4][G], m2[4][G], m3[4][G];
#pragma unroll
    for (int k = 0; k < 4; k++)
#pragma unroll
        for (int g = 0; g < G; g++) {
            m1[k][g] = 0; m2[k][g] = 0; m3[k][g] = 0;
        }
    unsigned p1[4] = {0,0,0,0}, p2[4] = {0,0,0,0}, p3[4] = {0,0,0,0};
    unsigned ss1l[4] = {0,0,0,0}, ss1h[4] = {0,0,0,0};
    unsigned ss2l[4] = {0,0,0,0}, ss2h[4] = {0,0,0,0};
    unsigned ss3l[4] = {0,0,0,0}, ss3h[4] = {0,0,0,0};

    F4U bq2, bq3;
    bq2.f = __ldg(reinterpret_cast<const float4*>(b2) + tid);
    bq3.f = __ldg(reinterpret_cast<const float4*>(b3) + tid);

    const float4* W14 = reinterpret_cast<const float4*>(W1);
    const float4* base2 = reinterpret_cast<const float4*>(g_W2T) + tid;
    const float4* base3 = reinterpret_cast<const float4*>(g_W3T) + tid;

    // constant layer-1 drive (t >= 12 uses input slice at 776): to SMEM
    if (tid < G * 8)
        xsh[tid] = __ldg(input + (n0 + (tid >> 3)) * 784 + 776 + (tid & 7));
    __syncthreads();
    {
        float4 bq1 = __ldg(reinterpret_cast<const float4*>(b1) + tid);
        float w1r[4][8];
#pragma unroll
        for (int k = 0; k < 4; k++) {
            float4 a = __ldg(W14 + (h0 + k) * 2);
            float4 c = __ldg(W14 + (h0 + k) * 2 + 1);
            w1r[k][0] = a.x; w1r[k][1] = a.y; w1r[k][2] = a.z; w1r[k][3] = a.w;
            w1r[k][4] = c.x; w1r[k][5] = c.y; w1r[k][6] = c.z; w1r[k][7] = c.w;
        }
        float bb[4] = {bq1.x, bq1.y, bq1.z, bq1.w};
#pragma unroll
        for (int g = 0; g < G; g++) {
            const float* x = &xsh[g * 8];
            float s[4];
#pragma unroll
            for (int k = 0; k < 4; k++) {
                float acc = bb[k];
#pragma unroll
                for (int i = 0; i < 8; i++) acc += x[i] * w1r[k][i];
                s[k] = acc;
            }
            F4U pk;
            pk.f = make_float4(s[0], s[1], s[2], s[3]);
            dcsh[g * NTHR + tid] = make_ulonglong2(pk.u[0], pk.u[1]);
        }
    }
    __syncthreads();

    for (int t = 0; t < TSTEPS; t++) {
        // ---------- layer 1 drive (packed pairs: L = units 0,1; H = 2,3) ---
        unsigned long long d1L[G], d1H[G];
        if (t < 12) {
            if (tid < G * 8)
                xsh[tid] =
                    __ldg(input + (n0 + (tid >> 3)) * 784 + t * 8 + (tid & 7));
            __syncthreads();
            float4 bq1 = __ldg(reinterpret_cast<const float4*>(b1) + tid);
            float w1r[4][8];
#pragma unroll
            for (int k = 0; k < 4; k++) {
                float4 a = __ldg(W14 + (h0 + k) * 2);
                float4 c = __ldg(W14 + (h0 + k) * 2 + 1);
                w1r[k][0] = a.x; w1r[k][1] = a.y; w1r[k][2] = a.z; w1r[k][3] = a.w;
                w1r[k][4] = c.x; w1r[k][5] = c.y; w1r[k][6] = c.z; w1r[k][7] = c.w;
            }
            float bb[4] = {bq1.x, bq1.y, bq1.z, bq1.w};
#pragma unroll
            for (int g = 0; g < G; g++) {
                const float* x = &xsh[g * 8];
                float s[4];
#pragma unroll
                for (int k = 0; k < 4; k++) {
                    float acc = bb[k];
#pragma unroll
                    for (int i = 0; i < 8; i++) acc += x[i] * w1r[k][i];
                    s[k] = acc;
                }
                F4U pk;
                pk.f = make_float4(s[0], s[1], s[2], s[3]);
                d1L[g] = pk.u[0];
                d1H[g] = pk.u[1];
            }
            __syncthreads();
        } else {
#pragma unroll
            for (int g = 0; g < G; g++) {
                ulonglong2 v = dcsh[g * NTHR + tid];
                d1L[g] = v.x;
                d1H[g] = v.y;
            }
        }

        // ---------- layer 1 update (cycle 2) ----------
        upd_pair(m1[0], m1[1], d1L, (u[0] & 1) == 0, (u[1] & 1) == 0, p1[0], p1[1]);
        upd_pair(m1[2], m1[3], d1H, (u[2] & 1) == 0, (u[3] & 1) == 0, p1[2], p1[3]);
#pragma unroll
        for (int k = 0; k < 4; k++) {
            ss1l[k] += spread4(p1[k]);
            ss1h[k] += spread4(p1[k] >> 4);
        }

        int excl, cnt;
        {
            int cl = (p1[0] ? 1 : 0) + (p1[1] ? 1 : 0) + (p1[2] ? 1 : 0) +
                     (p1[3] ? 1 : 0);
            block_scan(cl, tid, s_warp, excl, cnt);
            int p = excl;
#pragma unroll
            for (int k = 0; k < 4; k++)
                if (p1[k]) listA[p++] = (p1[k] << 10) | (unsigned)(h0 + k);
        }
        __syncthreads();

        // ---------- layer 2: gather + update (cycle 3) ----------
        unsigned long long accL[G], accH[G];
#pragma unroll
        for (int g = 0; g < G; g++) { accL[g] = bq2.u[0]; accH[g] = bq2.u[1]; }
        gather(listA, cnt, base2, accL, accH);

        upd_pair(m2[0], m2[1], accL, r3[0] == 0, r3[1] == 0, p2[0], p2[1]);
        upd_pair(m2[2], m2[3], accH, r3[2] == 0, r3[3] == 0, p2[2], p2[3]);
#pragma unroll
        for (int k = 0; k < 4; k++) {
            ss2l[k] += spread4(p2[k]);
            ss2h[k] += spread4(p2[k] >> 4);
        }

        {
            int cl = (p2[0] ? 1 : 0) + (p2[1] ? 1 : 0) + (p2[2] ? 1 : 0) +
                     (p2[3] ? 1 : 0);
            block_scan(cl, tid, s_warp, excl, cnt);
            int p = excl;
#pragma unroll
            for (int k = 0; k < 4; k++)
                if (p2[k]) listB[p++] = (p2[k] << 10) | (unsigned)(h0 + k);
        }
        __syncthreads();

        // ---------- layer 3: gather + update (cycle 4) ----------
#pragma unroll
        for (int g = 0; g < G; g++) { accL[g] = bq3.u[0]; accH[g] = bq3.u[1]; }
        gather(listB, cnt, base3, accL, accH);

        upd_pair(m3[0], m3[1], accL, (u[0] & 3) == 0, (u[1] & 3) == 0, p3[0], p3[1]);
        upd_pair(m3[2], m3[3], accH, (u[2] & 3) == 0, (u[3] & 3) == 0, p3[2], p3[3]);
#pragma unroll
        for (int k = 0; k < 4; k++) {
            ss3l[k] += spread4(p3[k]);
            ss3h[k] += spread4(p3[k] >> 4);
        }

#pragma unroll
        for (int k = 0; k < 4; k++) {
            if (++u[k] == 98) { u[k] = 0; r3[k] = 0; }
            else if (++r3[k] == 3) r3[k] = 0;
        }
    }

    // ------------------------- epilogue -------------------------
    const float inv = 1.0f / 98.0f;

    // hidden_spk = ss / 98; float4 per (layer, sample)
#pragma unroll
    for (int g = 0; g < G; g++) {
        int sh = 8 * (g & 3);
        const unsigned* l1 = (g < 4) ? ss1l : ss1h;
        const unsigned* l2 = (g < 4) ? ss2l : ss2h;
        const unsigned* l3 = (g < 4) ? ss3l : ss3h;
        float4 v1 = make_float4((float)((l1[0] >> sh) & 255u) * inv,
                                (float)((l1[1] >> sh) & 255u) * inv,
                                (float)((l1[2] >> sh) & 255u) * inv,
                                (float)((l1[3] >> sh) & 255u) * inv);
        float4 v2 = make_float4((float)((l2[0] >> sh) & 255u) * inv,
                                (float)((l2[1] >> sh) & 255u) * inv,
                                (float)((l2[2] >> sh) & 255u) * inv,
                                (float)((l2[3] >> sh) & 255u) * inv);
        float4 v3 = make_float4((float)((l3[0] >> sh) & 255u) * inv,
                                (float)((l3[1] >> sh) & 255u) * inv,
                                (float)((l3[2] >> sh) & 255u) * inv,
                                (float)((l3[3] >> sh) & 255u) * inv);
        *reinterpret_cast<float4*>(out + 10240 + 0 * 1048576 + (n0 + g) * HID + h0) = v1;
        *reinterpret_cast<float4*>(out + 10240 + 1 * 1048576 + (n0 + g) * HID + h0) = v2;
        *reinterpret_cast<float4*>(out + 10240 + 2 * 1048576 + (n0 + g) * HID + h0) = v3;
    }

    // spike counts as floats for output GEMM
    float s3[4][G];
#pragma unroll
    for (int k = 0; k < 4; k++)
#pragma unroll
        for (int g = 0; g < G; g++)
            s3[k][g] = (float)(((g < 4 ? ss3l[k] : ss3h[k]) >> (8 * (g & 3))) & 255u);

    const int lane = tid & 31, wid = tid >> 5;

    // outputs[n] = (ss3 @ W4^T)/98 + b4
    for (int o = 0; o < 10; o++) {
        float4 w4 = __ldg(reinterpret_cast<const float4*>(W4 + o * HID) + tid);
#pragma unroll
        for (int half = 0; half < 2; half++) {
            float4 v;
            v.x = s3[0][half * 4 + 0] * w4.x + s3[1][half * 4 + 0] * w4.y +
                  s3[2][half * 4 + 0] * w4.z + s3[3][half * 4 + 0] * w4.w;
            v.y = s3[0][half * 4 + 1] * w4.x + s3[1][half * 4 + 1] * w4.y +
                  s3[2][half * 4 + 1] * w4.z + s3[3][half * 4 + 1] * w4.w;
            v.z = s3[0][half * 4 + 2] * w4.x + s3[1][half * 4 + 2] * w4.y +
                  s3[2][half * 4 + 2] * w4.z + s3[3][half * 4 + 2] * w4.w;
            v.w = s3[0][half * 4 + 3] * w4.x + s3[1][half * 4 + 3] * w4.y +
                  s3[2][half * 4 + 3] * w4.z + s3[3][half * 4 + 3] * w4.w;
#pragma unroll
            for (int off = 16; off > 0; off >>= 1) {
                v.x += __shfl_down_sync(0xffffffffu, v.x, off);
                v.y += __shfl_down_sync(0xffffffffu, v.y, off);
                v.z += __shfl_down_sync(0xffffffffu, v.z, off);
                v.w += __shfl_down_sync(0xffffffffu, v.w, off);
            }
            if (lane == 0) s_red4[wid] = v;
            __syncthreads();
            if (tid == 0) {
                float4 s = make_float4(0, 0, 0, 0);
#pragma unroll
                for (int w = 0; w < 8; w++) {
                    s.x += s_red4[w].x; s.y += s_red4[w].y;
                    s.z += s_red4[w].z; s.w += s_red4[w].w;
                }
                float bo = __ldg(b4 + o);
                out[(n0 + half * 4 + 0) * 10 + o] = s.x / 98.0f + bo;
                out[(n0 + half * 4 + 1) * 10 + o] = s.y / 98.0f + bo;
                out[(n0 + half * 4 + 2) * 10 + o] = s.z / 98.0f + bo;
                out[(n0 + half * 4 + 3) * 10 + o] = s.w / 98.0f + bo;
            }
            __syncthreads();
        }
    }

    // layer firing-rate partial sums (exact integers in fp32)
    unsigned c1 = 0, c2 = 0, c3 = 0;
#pragma unroll
    for (int k = 0; k < 4; k++) {
        c1 = bytesum(ss1l[k], c1); c1 = bytesum(ss1h[k], c1);
        c2 = bytesum(ss2l[k], c2); c2 = bytesum(ss2h[k], c2);
        c3 = bytesum(ss3l[k], c3); c3 = bytesum(ss3h[k], c3);
    }
    {
        float4 v = make_float4((float)c1, (float)c2, (float)c3, 0.0f);
#pragma unroll
        for (int off = 16; off > 0; off >>= 1) {
            v.x += __shfl_down_sync(0xffffffffu, v.x, off);
            v.y += __shfl_down_sync(0xffffffffu, v.y, off);
            v.z += __shfl_down_sync(0xffffffffu, v.z, off);
        }
        if (lane == 0) s_red4[wid] = v;
        __syncthreads();
        if (tid == 0) {
            float s0 = 0, s1 = 0, s2 = 0;
#pragma unroll
            for (int w = 0; w < 8; w++) {
                s0 += s_red4[w].x; s1 += s_red4[w].y; s2 += s_red4[w].z;
            }
            atomicAdd(&g_fr[0], s0);
            atomicAdd(&g_fr[1], s1);
            atomicAdd(&g_fr[2], s2);
        }
    }
}

__global__ void finalize_kernel(float* __restrict__ out) {
    if (threadIdx.x < 3)
        out[3155968 + threadIdx.x] = g_fr[threadIdx.x] / 102760448.0f;
}

extern "C" void kernel_launch(void* const* d_in, const int* in_sizes, int n_in,
                              void* d_out, int out_size) {
    const float* input = (const float*)d_in[0];
    const float* W1 = (const float*)d_in[1];
    const float* b1 = (const float*)d_in[2];
    const float* W2 = (const float*)d_in[3];
    const float* b2 = (const float*)d_in[4];
    const float* W3 = (const float*)d_in[5];
    const float* b3 = (const float*)d_in[6];
    const float* W4 = (const float*)d_in[7];
    const float* b4 = (const float*)d_in[8];
    (void)in_sizes; (void)n_in; (void)out_size;

    dim3 pgrid(HID / 32, HID / 32, 2);
    prep_kernel<<<pgrid, dim3(32, 32)>>>(W2, W3);
    snn_kernel<<<NCTA, NTHR>>>(input, W1, b1, b2, b3, W4, b4, (float*)d_out);
    finalize_kernel<<<1, 32>>>((float*)d_out);
}